// round 10
// baseline (speedup 1.0000x reference)
#include <cuda_runtime.h>

// DeepLK inverse-compositional LK, B=8, k=8, 256x256, 10 iterations.
// R9: one PIXEL per thread (2048-block iter grid, lower reg pressure, more
// latency-hiding warps) + X/Y factored out of the channel accumulation
// (only S_gx, S_gy accumulated; 8-vector expanded once at the end).

#define BB   8
#define KK   8
#define HH   256
#define WW   256
#define HWSZ (HH * WW)
#define NPB  (KK * HWSZ)     // 524288 elements per batch
#define CPB  128             // hmat: blocks per batch
#define NBLK (BB * CPB)      // hmat grid = 1024
#define CPB2 256             // iter: blocks per batch
#define NBLK2 (BB * CPB2)    // iter grid = 2048
#define TPB  256

// mask thresholds: xn > -1+2/256  <=>  xw > 0.99609375 ; xw < 254.00390625
#define MLO 0.99609375f
#define MHI 254.00390625f

// ---- device scratch (static; no allocations) ----
__device__ double g_hpart[NBLK][36];
__device__ double g_vpart[NBLK2][8];
__device__ double g_invH[BB][64];
__device__ double g_p[BB][8];
__device__ double g_dp[BB][8];
__device__ float  g_Hm[BB][9];
__device__ unsigned int g_cnt[2];
__device__ float  g_gxy[(size_t)BB * NPB * 2];   // interleaved gx,gy per pixel

// -------------------------------------------------------------------------
__global__ void init_kernel(const float* __restrict__ initp) {
    int t = threadIdx.x;
    if (t < 64) {
        int b = t >> 3, i = t & 7;
        float pv = initp[t];
        g_p[b][i]  = (double)pv;
        g_dp[b][i] = 1.0;
        g_Hm[b][i] = pv + ((i == 0 || i == 4) ? 1.0f : 0.0f);
        if (i == 0) g_Hm[b][8] = 1.0f;
    }
    if (t == 64) { g_cnt[0] = 0; g_cnt[1] = 0; }
}

// -------------------------------------------------------------------------
// Pass 1: per-batch normal matrix H (36 upper-tri entries) + gradient dump.
__global__ __launch_bounds__(TPB) void hmat_kernel(const float* __restrict__ temp) {
    int b     = blockIdx.x / CPB;
    int chunk = blockIdx.x % CPB;
    const float* T = temp + (size_t)b * NPB;
    float* gout = g_gxy + (size_t)b * NPB * 2;

    float acc[36];
#pragma unroll
    for (int i = 0; i < 36; i++) acc[i] = 0.f;

    for (int n = chunk * TPB + threadIdx.x; n < NPB; n += CPB * TPB) {
        int c   = n >> 16;
        int rem = n & (HWSZ - 1);
        int y   = rem >> 8;
        int x   = rem & (WW - 1);
        const float* Tc   = T + c * HWSZ;
        const float* Trow = Tc + y * WW;
        int xm = (x > 0) ? x - 1 : 0;
        int xp = (x < WW - 1) ? x + 1 : WW - 1;
        int ym = (y > 0) ? y - 1 : 0;
        int yp = (y < HH - 1) ? y + 1 : HH - 1;
        float gx = 0.5f * (Trow[xp] - Trow[xm]);
        float gy = 0.5f * (Tc[yp * WW + x] - Tc[ym * WW + x]);
        *(float2*)(gout + 2 * (size_t)n) = make_float2(gx, gy);
        float X = (float)x - 127.5f;
        float Y = (float)y - 127.5f;
        float J[8];
        J[0] = X * gx; J[1] = Y * gx; J[2] = gx;
        J[3] = X * gy; J[4] = Y * gy; J[5] = gy;
        J[6] = -(X * J[0] + Y * J[3]);
        J[7] = -(X * J[1] + Y * J[4]);
        int idx = 0;
#pragma unroll
        for (int i = 0; i < 8; i++)
#pragma unroll
            for (int j = i; j < 8; j++)
                acc[idx++] += J[i] * J[j];
    }

    __shared__ float swh[8][36];
    int lane = threadIdx.x & 31, wid = threadIdx.x >> 5;
#pragma unroll
    for (int i = 0; i < 36; i++) {
        float v = acc[i];
#pragma unroll
        for (int o = 16; o > 0; o >>= 1) v += __shfl_down_sync(0xffffffffu, v, o);
        if (lane == 0) swh[wid][i] = v;
    }
    __syncthreads();
    if (threadIdx.x < 36) {
        double s = 0.0;
#pragma unroll
        for (int w = 0; w < 8; w++) s += (double)swh[w][threadIdx.x];
        g_hpart[blockIdx.x][threadIdx.x] = s;
    }
    __threadfence();
    __syncthreads();

    __shared__ bool sLast;
    if (threadIdx.x == 0) {
        unsigned old = atomicAdd(&g_cnt[0], 1u);
        sLast = (old == gridDim.x - 1);
        if (sLast) g_cnt[0] = 0;
    }
    __syncthreads();
    if (!sLast) return;
    __threadfence();

    __shared__ double sH[BB][36];
    for (int e = threadIdx.x; e < BB * 36; e += blockDim.x) {
        int bb = e / 36, i = e % 36;
        double s = 0.0;
        for (int ch = 0; ch < CPB; ch++) s += g_hpart[bb * CPB + ch][i];
        sH[bb][i] = s;
    }
    __syncthreads();

    // Gauss-Jordan inversion (SPD, no pivoting), 8 batches x 16 columns.
    __shared__ double aug[BB][8][17];
    int t  = threadIdx.x;
    int bb = t >> 4;
    int j  = t & 15;
    if (t < 128) {
        for (int r = 0; r < 8; r++) {
            double v;
            if (j < 8) {
                int i  = (r < j) ? r : j;
                int jj = (r < j) ? j : r;
                int idx = i * 8 + jj - (i * (i + 1)) / 2;
                v = sH[bb][idx];
            } else {
                v = ((j - 8) == r) ? 1.0 : 0.0;
            }
            aug[bb][r][j] = v;
        }
    }
    __syncthreads();
    for (int k = 0; k < 8; k++) {
        double pivinv = 0.0;
        if (t < 128) pivinv = 1.0 / aug[bb][k][k];
        __syncthreads();
        if (t < 128) aug[bb][k][j] *= pivinv;
        __syncthreads();
        double f[8];
        if (t < 128) {
#pragma unroll
            for (int i = 0; i < 8; i++) f[i] = aug[bb][i][k];
        }
        __syncthreads();
        if (t < 128) {
#pragma unroll
            for (int i = 0; i < 8; i++)
                if (i != k) aug[bb][i][j] -= f[i] * aug[bb][k][j];
        }
        __syncthreads();
    }
    if (t < 128 && j >= 8) {
        for (int r = 0; r < 8; r++)
            g_invH[bb][r * 8 + (j - 8)] = aug[bb][r][j];
    }
}

// -------------------------------------------------------------------------
// One LK iteration. Each thread: ONE pixel x all 8 channels.
// Only S_gx = sum_c gx*r, S_gy = sum_c gy*r accumulated; X/Y factored out.
__global__ __launch_bounds__(TPB, 6) void iter_kernel(const float* __restrict__ img,
                                                      const float* __restrict__ temp,
                                                      const int* __restrict__ maxItr,
                                                      int iter) {
    bool act = (maxItr == 0) || (iter < __ldg(maxItr));
    int b  = blockIdx.x >> 8;                          // / CPB2
    int pi = ((blockIdx.x & 255) << 8) | threadIdx.x;  // 0..65535 pixel index

    float acc[8];
#pragma unroll
    for (int i = 0; i < 8; i++) acc[i] = 0.f;

    if (act) {
        int y = pi >> 8;
        int x = pi & 255;
        int rowoff = y * WW + x;
        const float* T = temp + (size_t)b * NPB + rowoff;
        const float* I = img  + (size_t)b * NPB;
        const float* G = g_gxy + 2 * ((size_t)b * NPB + rowoff);
        float h0 = g_Hm[b][0], h1 = g_Hm[b][1], h2 = g_Hm[b][2];
        float h3 = g_Hm[b][3], h4 = g_Hm[b][4], h5 = g_Hm[b][5];
        float h6 = g_Hm[b][6], h7 = g_Hm[b][7], h8 = g_Hm[b][8];

        float Y = (float)y - 127.5f;
        float X = (float)x - 127.5f;

        // per-pixel precompute (once, reused by all 8 channels)
        float Z = h6 * X + h7 * Y + h8;
        float invZ = __fdividef(1.0f, Z);
        float xw = (h0 * X + h1 * Y + h2) * invZ + 127.5f;
        float yw = (h3 * X + h4 * Y + h5) * invZ + 127.5f;

        float x0f = floorf(xw), y0f = floorf(yw);
        int   x0  = (int)x0f,  y0  = (int)y0f;
        float fx  = xw - x0f,  fy  = yw - y0f;

        bool vx0 = (x0 >= 0) && (x0 <= WW - 1);
        bool vx1 = (x0 + 1 >= 0) && (x0 + 1 <= WW - 1);
        bool vy0 = (y0 >= 0) && (y0 <= HH - 1);
        bool vy1 = (y0 + 1 >= 0) && (y0 + 1 <= HH - 1);
        int xc0 = vx0 ? x0     : 0;
        int xc1 = vx1 ? x0 + 1 : 0;
        int yc0 = vy0 ? y0     : 0;
        int yc1 = vy1 ? y0 + 1 : 0;
        int o00 = yc0 * WW + xc0;
        int o01 = yc0 * WW + xc1;
        int o10 = yc1 * WW + xc0;
        int o11 = yc1 * WW + xc1;
        float wx0 = vx0 ? (1.f - fx) : 0.f;
        float wx1 = vx1 ? fx         : 0.f;
        float wy0 = vy0 ? (1.f - fy) : 0.f;
        float wy1 = vy1 ? fy         : 0.f;
        float w00 = wx0 * wy0;
        float w01 = wx1 * wy0;
        float w10 = wx0 * wy1;
        float w11 = wx1 * wy1;
        bool m = (xw > MLO) & (xw < MHI) & (yw > MLO) & (yw < MHI);
        float tsel = m ? 1.f : 0.f;

        // channel loop: gathers + a handful of FMAs only
        float Sgx = 0.f, Sgy = 0.f;
#pragma unroll
        for (int c = 0; c < KK; c++) {
            const float* Ic = I + c * HWSZ;
            float  tc = T[c * HWSZ];
            float2 g  = *(const float2*)(G + 2 * c * HWSZ);
            float Fi = w00 * Ic[o00] + w01 * Ic[o01]
                     + w10 * Ic[o10] + w11 * Ic[o11];
            float r = Fi - tsel * tc;
            Sgx += g.x * r;
            Sgy += g.y * r;
        }

        // expand the 8-vector once
        acc[0] = X * Sgx;
        acc[1] = Y * Sgx;
        acc[2] = Sgx;
        acc[3] = X * Sgy;
        acc[4] = Y * Sgy;
        acc[5] = Sgy;
        float s = X * Sgx + Y * Sgy;
        acc[6] = -X * s;
        acc[7] = -Y * s;
    }

    // block reduction
    __shared__ float swv[8][8];
    int lane = threadIdx.x & 31, wid = threadIdx.x >> 5;
#pragma unroll
    for (int i = 0; i < 8; i++) {
        float v = acc[i];
#pragma unroll
        for (int o = 16; o > 0; o >>= 1) v += __shfl_down_sync(0xffffffffu, v, o);
        if (lane == 0) swv[wid][i] = v;
    }
    __syncthreads();
    if (threadIdx.x < 8) {
        double s = 0.0;
#pragma unroll
        for (int w = 0; w < 8; w++) s += (double)swv[w][threadIdx.x];
        g_vpart[blockIdx.x][threadIdx.x] = s;
    }
    __threadfence();
    __syncthreads();

    __shared__ bool sLast;
    if (threadIdx.x == 0) {
        unsigned old = atomicAdd(&g_cnt[1], 1u);
        sLast = (old == gridDim.x - 1);
        if (sLast) g_cnt[1] = 0;
    }
    __syncthreads();
    if (!sLast) return;
    __threadfence();

    // fused update: dp = invH * v; freeze gate; p -= dp; rebuild Hm.
    __shared__ double sv[BB][8];
    int t = threadIdx.x;
    if (t < 64) {
        int bb = t >> 3, q = t & 7;
        double s = 0.0;
        for (int ch = 0; ch < CPB2; ch++) s += g_vpart[bb * CPB2 + ch][q];
        sv[bb][q] = s;
    }
    __syncthreads();

    bool have = act && (t < 64);
    double d = 0.0, ns = 0.0;
    int bb = t >> 3, row = t & 7;
    if (have) {
#pragma unroll
        for (int q = 0; q < 8; q++) d += g_invH[bb][row * 8 + q] * sv[bb][q];
        if (row >= 6) d = 0.0;
#pragma unroll
        for (int q = 0; q < 8; q++) { double dq = g_dp[bb][q]; ns += dq * dq; }
    }
    __syncthreads();
    if (have) {
        bool actb  = (sqrt(ns) > 1e-3);
        double dp2 = actb ? d : 0.0;
        double pnew = g_p[bb][row] - dp2;
        g_p[bb][row]  = pnew;
        g_dp[bb][row] = dp2;
        g_Hm[bb][row] = (float)pnew + ((row == 0 || row == 4) ? 1.0f : 0.0f);
        if (row == 0) g_Hm[bb][8] = 1.0f;
    }
}

// -------------------------------------------------------------------------
__global__ void fin_kernel(float* __restrict__ out, int out_size) {
    int t = threadIdx.x;
    if (t < 64 && t < out_size)
        out[t] = (float)g_p[t >> 3][t & 7];
    if (t < 72 && (64 + t) < out_size) {
        int bb = t / 9, e = t % 9;
        float v;
        if (e < 8) v = (float)g_p[bb][e] + ((e == 0 || e == 4) ? 1.0f : 0.0f);
        else       v = 1.0f;
        out[64 + t] = v;
    }
}

// -------------------------------------------------------------------------
extern "C" void kernel_launch(void* const* d_in, const int* in_sizes, int n_in,
                              void* d_out, int out_size) {
    const float* img   = (const float*)d_in[0];
    const float* temp  = (const float*)d_in[1];
    const float* initp = (const float*)d_in[2];
    const int*   maxit = (n_in >= 4) ? (const int*)d_in[3] : 0;
    (void)in_sizes;

    init_kernel<<<1, 128>>>(initp);
    hmat_kernel<<<NBLK, TPB>>>(temp);
    for (int it = 0; it < 10; it++)
        iter_kernel<<<NBLK2, TPB>>>(img, temp, maxit, it);
    fin_kernel<<<1, 128>>>((float*)d_out, out_size);
}

// round 15
// speedup vs baseline: 1.3387x; 1.3387x over previous
#include <cuda_runtime.h>

// DeepLK inverse-compositional LK, B=8, k=8, 256x256, 10 iterations.
// R14 (= R10 resubmit after infra failure): R8's pixel-pair layout
// (vectorized temp/grad loads, deep gather MLP) + factored accumulation
// (only S_gx,S_gy per pixel in the channel loop; 8-vector expanded once).

#define BB   8
#define KK   8
#define HH   256
#define WW   256
#define HWSZ (HH * WW)
#define NPB  (KK * HWSZ)     // 524288 elements per batch
#define CPB  128             // blocks per batch
#define TPB  256
#define NBLK (BB * CPB)      // 1024 blocks

// mask thresholds: xn > -1+2/256  <=>  xw > 0.99609375 ; xw < 254.00390625
#define MLO 0.99609375f
#define MHI 254.00390625f

// ---- device scratch (static; no allocations) ----
__device__ double g_hpart[NBLK][36];
__device__ double g_vpart[NBLK][8];
__device__ double g_invH[BB][64];
__device__ double g_p[BB][8];
__device__ double g_dp[BB][8];
__device__ float  g_Hm[BB][9];
__device__ unsigned int g_cnt[2];
__device__ float  g_gxy[(size_t)BB * NPB * 2];   // interleaved gx,gy per pixel

// -------------------------------------------------------------------------
__global__ void init_kernel(const float* __restrict__ initp) {
    int t = threadIdx.x;
    if (t < 64) {
        int b = t >> 3, i = t & 7;
        float pv = initp[t];
        g_p[b][i]  = (double)pv;
        g_dp[b][i] = 1.0;
        g_Hm[b][i] = pv + ((i == 0 || i == 4) ? 1.0f : 0.0f);
        if (i == 0) g_Hm[b][8] = 1.0f;
    }
    if (t == 64) { g_cnt[0] = 0; g_cnt[1] = 0; }
}

// -------------------------------------------------------------------------
// Pass 1: per-batch normal matrix H (36 upper-tri entries) + gradient dump.
__global__ __launch_bounds__(TPB) void hmat_kernel(const float* __restrict__ temp) {
    int b     = blockIdx.x / CPB;
    int chunk = blockIdx.x % CPB;
    const float* T = temp + (size_t)b * NPB;
    float* gout = g_gxy + (size_t)b * NPB * 2;

    float acc[36];
#pragma unroll
    for (int i = 0; i < 36; i++) acc[i] = 0.f;

    for (int n = chunk * TPB + threadIdx.x; n < NPB; n += CPB * TPB) {
        int c   = n >> 16;
        int rem = n & (HWSZ - 1);
        int y   = rem >> 8;
        int x   = rem & (WW - 1);
        const float* Tc   = T + c * HWSZ;
        const float* Trow = Tc + y * WW;
        int xm = (x > 0) ? x - 1 : 0;
        int xp = (x < WW - 1) ? x + 1 : WW - 1;
        int ym = (y > 0) ? y - 1 : 0;
        int yp = (y < HH - 1) ? y + 1 : HH - 1;
        float gx = 0.5f * (Trow[xp] - Trow[xm]);
        float gy = 0.5f * (Tc[yp * WW + x] - Tc[ym * WW + x]);
        *(float2*)(gout + 2 * (size_t)n) = make_float2(gx, gy);
        float X = (float)x - 127.5f;
        float Y = (float)y - 127.5f;
        float J[8];
        J[0] = X * gx; J[1] = Y * gx; J[2] = gx;
        J[3] = X * gy; J[4] = Y * gy; J[5] = gy;
        J[6] = -(X * J[0] + Y * J[3]);
        J[7] = -(X * J[1] + Y * J[4]);
        int idx = 0;
#pragma unroll
        for (int i = 0; i < 8; i++)
#pragma unroll
            for (int j = i; j < 8; j++)
                acc[idx++] += J[i] * J[j];
    }

    __shared__ float swh[8][36];
    int lane = threadIdx.x & 31, wid = threadIdx.x >> 5;
#pragma unroll
    for (int i = 0; i < 36; i++) {
        float v = acc[i];
#pragma unroll
        for (int o = 16; o > 0; o >>= 1) v += __shfl_down_sync(0xffffffffu, v, o);
        if (lane == 0) swh[wid][i] = v;
    }
    __syncthreads();
    if (threadIdx.x < 36) {
        double s = 0.0;
#pragma unroll
        for (int w = 0; w < 8; w++) s += (double)swh[w][threadIdx.x];
        g_hpart[blockIdx.x][threadIdx.x] = s;
    }
    __threadfence();
    __syncthreads();

    __shared__ bool sLast;
    if (threadIdx.x == 0) {
        unsigned old = atomicAdd(&g_cnt[0], 1u);
        sLast = (old == gridDim.x - 1);
        if (sLast) g_cnt[0] = 0;
    }
    __syncthreads();
    if (!sLast) return;
    __threadfence();

    __shared__ double sH[BB][36];
    for (int e = threadIdx.x; e < BB * 36; e += blockDim.x) {
        int bb = e / 36, i = e % 36;
        double s = 0.0;
        for (int ch = 0; ch < CPB; ch++) s += g_hpart[bb * CPB + ch][i];
        sH[bb][i] = s;
    }
    __syncthreads();

    // Gauss-Jordan inversion (SPD, no pivoting), 8 batches x 16 columns.
    __shared__ double aug[BB][8][17];
    int t  = threadIdx.x;
    int bb = t >> 4;
    int j  = t & 15;
    if (t < 128) {
        for (int r = 0; r < 8; r++) {
            double v;
            if (j < 8) {
                int i  = (r < j) ? r : j;
                int jj = (r < j) ? j : r;
                int idx = i * 8 + jj - (i * (i + 1)) / 2;
                v = sH[bb][idx];
            } else {
                v = ((j - 8) == r) ? 1.0 : 0.0;
            }
            aug[bb][r][j] = v;
        }
    }
    __syncthreads();
    for (int k = 0; k < 8; k++) {
        double pivinv = 0.0;
        if (t < 128) pivinv = 1.0 / aug[bb][k][k];
        __syncthreads();
        if (t < 128) aug[bb][k][j] *= pivinv;
        __syncthreads();
        double f[8];
        if (t < 128) {
#pragma unroll
            for (int i = 0; i < 8; i++) f[i] = aug[bb][i][k];
        }
        __syncthreads();
        if (t < 128) {
#pragma unroll
            for (int i = 0; i < 8; i++)
                if (i != k) aug[bb][i][j] -= f[i] * aug[bb][k][j];
        }
        __syncthreads();
    }
    if (t < 128 && j >= 8) {
        for (int r = 0; r < 8; r++)
            g_invH[bb][r * 8 + (j - 8)] = aug[bb][r][j];
    }
}

// -------------------------------------------------------------------------
// One LK iteration. Each thread: one pixel-pair x all 8 channels.
// Channel loop accumulates only S_gx,S_gy per pixel; X/Y expansion at end.
__global__ __launch_bounds__(TPB, 4) void iter_kernel(const float* __restrict__ img,
                                                      const float* __restrict__ temp,
                                                      const int* __restrict__ maxItr,
                                                      int iter) {
    bool act = (maxItr == 0) || (iter < __ldg(maxItr));
    int b = blockIdx.x >> 7;                       // / CPB
    int pi = ((blockIdx.x & 127) << 8) | threadIdx.x;   // 0..32767 pair index

    float acc[8];
#pragma unroll
    for (int i = 0; i < 8; i++) acc[i] = 0.f;

    if (act) {
        int y = pi >> 7;
        int x = (pi & 127) << 1;
        int rowoff = y * WW + x;
        const float* T = temp + (size_t)b * NPB + rowoff;
        const float* I = img  + (size_t)b * NPB;
        const float* G = g_gxy + 2 * ((size_t)b * NPB + rowoff);
        float h0 = g_Hm[b][0], h1 = g_Hm[b][1], h2 = g_Hm[b][2];
        float h3 = g_Hm[b][3], h4 = g_Hm[b][4], h5 = g_Hm[b][5];
        float h6 = g_Hm[b][6], h7 = g_Hm[b][7], h8 = g_Hm[b][8];

        float Y  = (float)y - 127.5f;
        float X0 = (float)x - 127.5f;

        // per-pixel precompute (2 pixels)
        int   o00[2], o01[2], o10[2], o11[2];
        float w00[2], w01[2], w10[2], w11[2], tsel[2];
#pragma unroll
        for (int j = 0; j < 2; j++) {
            float X = X0 + (float)j;
            float Z = h6 * X + h7 * Y + h8;
            float invZ = __fdividef(1.0f, Z);
            float xw = (h0 * X + h1 * Y + h2) * invZ + 127.5f;
            float yw = (h3 * X + h4 * Y + h5) * invZ + 127.5f;

            float x0f = floorf(xw), y0f = floorf(yw);
            int   x0  = (int)x0f,  y0  = (int)y0f;
            float fx  = xw - x0f,  fy  = yw - y0f;

            bool vx0 = (x0 >= 0) && (x0 <= WW - 1);
            bool vx1 = (x0 + 1 >= 0) && (x0 + 1 <= WW - 1);
            bool vy0 = (y0 >= 0) && (y0 <= HH - 1);
            bool vy1 = (y0 + 1 >= 0) && (y0 + 1 <= HH - 1);
            int xc0 = vx0 ? x0     : 0;
            int xc1 = vx1 ? x0 + 1 : 0;
            int yc0 = vy0 ? y0     : 0;
            int yc1 = vy1 ? y0 + 1 : 0;
            o00[j] = yc0 * WW + xc0;
            o01[j] = yc0 * WW + xc1;
            o10[j] = yc1 * WW + xc0;
            o11[j] = yc1 * WW + xc1;
            float wx0 = vx0 ? (1.f - fx) : 0.f;
            float wx1 = vx1 ? fx         : 0.f;
            float wy0 = vy0 ? (1.f - fy) : 0.f;
            float wy1 = vy1 ? fy         : 0.f;
            w00[j] = wx0 * wy0;
            w01[j] = wx1 * wy0;
            w10[j] = wx0 * wy1;
            w11[j] = wx1 * wy1;
            bool m = (xw > MLO) & (xw < MHI) & (yw > MLO) & (yw < MHI);
            tsel[j] = m ? 1.f : 0.f;
        }
        float X1 = X0 + 1.f;

        // channel loop: gathers + minimal FMAs (factored accumulation)
        float Sgx0 = 0.f, Sgy0 = 0.f, Sgx1 = 0.f, Sgy1 = 0.f;
#pragma unroll
        for (int c = 0; c < KK; c++) {
            const float* Ic = I + c * HWSZ;
            float2 t2 = __ldg((const float2*)(T + c * HWSZ));
            float4 g4 = __ldg((const float4*)(G + 2 * c * HWSZ));

            float Fi0 = w00[0] * __ldg(Ic + o00[0]) + w01[0] * __ldg(Ic + o01[0])
                      + w10[0] * __ldg(Ic + o10[0]) + w11[0] * __ldg(Ic + o11[0]);
            float Fi1 = w00[1] * __ldg(Ic + o00[1]) + w01[1] * __ldg(Ic + o01[1])
                      + w10[1] * __ldg(Ic + o10[1]) + w11[1] * __ldg(Ic + o11[1]);
            float r0 = Fi0 - tsel[0] * t2.x;
            float r1 = Fi1 - tsel[1] * t2.y;

            Sgx0 += g4.x * r0;
            Sgy0 += g4.y * r0;
            Sgx1 += g4.z * r1;
            Sgy1 += g4.w * r1;
        }

        // expand the 8-vector once
        acc[0] = X0 * Sgx0 + X1 * Sgx1;
        acc[1] = Y * (Sgx0 + Sgx1);
        acc[2] = Sgx0 + Sgx1;
        acc[3] = X0 * Sgy0 + X1 * Sgy1;
        acc[4] = Y * (Sgy0 + Sgy1);
        acc[5] = Sgy0 + Sgy1;
        float s0 = X0 * Sgx0 + Y * Sgy0;
        float s1 = X1 * Sgx1 + Y * Sgy1;
        acc[6] = -(X0 * s0 + X1 * s1);
        acc[7] = -Y * (s0 + s1);
    }

    // block reduction
    __shared__ float swv[8][8];
    int lane = threadIdx.x & 31, wid = threadIdx.x >> 5;
#pragma unroll
    for (int i = 0; i < 8; i++) {
        float v = acc[i];
#pragma unroll
        for (int o = 16; o > 0; o >>= 1) v += __shfl_down_sync(0xffffffffu, v, o);
        if (lane == 0) swv[wid][i] = v;
    }
    __syncthreads();
    if (threadIdx.x < 8) {
        double s = 0.0;
#pragma unroll
        for (int w = 0; w < 8; w++) s += (double)swv[w][threadIdx.x];
        g_vpart[blockIdx.x][threadIdx.x] = s;
    }
    __threadfence();
    __syncthreads();

    __shared__ bool sLast;
    if (threadIdx.x == 0) {
        unsigned old = atomicAdd(&g_cnt[1], 1u);
        sLast = (old == gridDim.x - 1);
        if (sLast) g_cnt[1] = 0;
    }
    __syncthreads();
    if (!sLast) return;
    __threadfence();

    // fused update: dp = invH * v; freeze gate; p -= dp; rebuild Hm.
    __shared__ double sv[BB][8];
    int t = threadIdx.x;
    if (t < 64) {
        int bb = t >> 3, q = t & 7;
        double s = 0.0;
        for (int ch = 0; ch < CPB; ch++) s += g_vpart[bb * CPB + ch][q];
        sv[bb][q] = s;
    }
    __syncthreads();

    bool have = act && (t < 64);
    double d = 0.0, ns = 0.0;
    int bb = t >> 3, row = t & 7;
    if (have) {
#pragma unroll
        for (int q = 0; q < 8; q++) d += g_invH[bb][row * 8 + q] * sv[bb][q];
        if (row >= 6) d = 0.0;
#pragma unroll
        for (int q = 0; q < 8; q++) { double dq = g_dp[bb][q]; ns += dq * dq; }
    }
    __syncthreads();
    if (have) {
        bool actb  = (sqrt(ns) > 1e-3);
        double dp2 = actb ? d : 0.0;
        double pnew = g_p[bb][row] - dp2;
        g_p[bb][row]  = pnew;
        g_dp[bb][row] = dp2;
        g_Hm[bb][row] = (float)pnew + ((row == 0 || row == 4) ? 1.0f : 0.0f);
        if (row == 0) g_Hm[bb][8] = 1.0f;
    }
}

// -------------------------------------------------------------------------
__global__ void fin_kernel(float* __restrict__ out, int out_size) {
    int t = threadIdx.x;
    if (t < 64 && t < out_size)
        out[t] = (float)g_p[t >> 3][t & 7];
    if (t < 72 && (64 + t) < out_size) {
        int bb = t / 9, e = t % 9;
        float v;
        if (e < 8) v = (float)g_p[bb][e] + ((e == 0 || e == 4) ? 1.0f : 0.0f);
        else       v = 1.0f;
        out[64 + t] = v;
    }
}

// -------------------------------------------------------------------------
extern "C" void kernel_launch(void* const* d_in, const int* in_sizes, int n_in,
                              void* d_out, int out_size) {
    const float* img   = (const float*)d_in[0];
    const float* temp  = (const float*)d_in[1];
    const float* initp = (const float*)d_in[2];
    const int*   maxit = (n_in >= 4) ? (const int*)d_in[3] : 0;
    (void)in_sizes;

    init_kernel<<<1, 128>>>(initp);
    hmat_kernel<<<NBLK, TPB>>>(temp);
    for (int it = 0; it < 10; it++)
        iter_kernel<<<NBLK, TPB>>>(img, temp, maxit, it);
    fin_kernel<<<1, 128>>>((float*)d_out, out_size);
}